// round 1
// baseline (speedup 1.0000x reference)
#include <cuda_runtime.h>
#include <cuda_bf16.h>
#include <math.h>

#define D 128
#define MAXN 50176   // 50000 padded to multiple of 128

__device__ float g_Q[MAXN * D];
__device__ float g_K[MAXN * D];
__device__ float g_V[MAXN * D];
__device__ float g_agg[MAXN * D];
__device__ float g_H[MAXN * D];

// ---------------------------------------------------------------------------
// zero kernel
// ---------------------------------------------------------------------------
__global__ void zero_kernel(float* __restrict__ p, int n) {
    int i = blockIdx.x * blockDim.x + threadIdx.x;
    if (i < n) p[i] = 0.0f;
}

// ---------------------------------------------------------------------------
// Tiled fp32 GEMM: O = X @ W^T  (+ optional bias + residual)
// X: [N,128], W: [128,128], O: [N,128]
// Block tile: 128 rows x 128 cols, BK=16, 256 threads, 8x8 microtile.
// NW = number of (W, O) pairs sharing the same X (fused QKV).
// ---------------------------------------------------------------------------
template <int NW, bool RESID>
__global__ void gemm_kernel(const float* __restrict__ X,
                            const float* __restrict__ Wa,
                            const float* __restrict__ Wb,
                            const float* __restrict__ Wc,
                            float* __restrict__ Oa,
                            float* __restrict__ Ob,
                            float* __restrict__ Oc,
                            const float* __restrict__ bias,
                            const float* __restrict__ resid,
                            int N)
{
    __shared__ float Xs[16][128];
    __shared__ float Ws[16][128];

    const int tid = threadIdx.x;          // 0..255
    const int tx = tid & 15;              // col group
    const int ty = tid >> 4;              // row group
    const int m0 = blockIdx.x * 128;

    const float* Wlist[3] = {Wa, Wb, Wc};
    float*       Olist[3] = {Oa, Ob, Oc};

#pragma unroll
    for (int w = 0; w < NW; ++w) {
        const float* Wp = Wlist[w];
        float*       Op = Olist[w];

        float acc[8][8];
#pragma unroll
        for (int i = 0; i < 8; ++i)
#pragma unroll
            for (int j = 0; j < 8; ++j) acc[i][j] = 0.0f;

        for (int kb = 0; kb < D; kb += 16) {
            // load X tile: 128 rows x 16 cols, transposed into Xs[k][m]
#pragma unroll
            for (int r = 0; r < 2; ++r) {
                int idx = tid + r * 256;       // 0..511 float4 slots
                int m = idx >> 2;              // 0..127
                int c = idx & 3;               // 0..3
                int gm = m0 + m;
                float4 f;
                if (gm < N) f = *(const float4*)&X[(size_t)gm * D + kb + c * 4];
                else        f = make_float4(0.f, 0.f, 0.f, 0.f);
                Xs[c * 4 + 0][m] = f.x;
                Xs[c * 4 + 1][m] = f.y;
                Xs[c * 4 + 2][m] = f.z;
                Xs[c * 4 + 3][m] = f.w;
            }
            // load W tile: Ws[k][j] = W[j][kb+k]
#pragma unroll
            for (int r = 0; r < 2; ++r) {
                int idx = tid + r * 256;
                int j = idx >> 2;
                int c = idx & 3;
                float4 f = *(const float4*)&Wp[(size_t)j * D + kb + c * 4];
                Ws[c * 4 + 0][j] = f.x;
                Ws[c * 4 + 1][j] = f.y;
                Ws[c * 4 + 2][j] = f.z;
                Ws[c * 4 + 3][j] = f.w;
            }
            __syncthreads();

#pragma unroll
            for (int k = 0; k < 16; ++k) {
                float4 a0 = *(const float4*)&Xs[k][ty * 8];
                float4 a1 = *(const float4*)&Xs[k][ty * 8 + 4];
                float4 b0 = *(const float4*)&Ws[k][tx * 8];
                float4 b1 = *(const float4*)&Ws[k][tx * 8 + 4];
                float a[8] = {a0.x, a0.y, a0.z, a0.w, a1.x, a1.y, a1.z, a1.w};
                float b[8] = {b0.x, b0.y, b0.z, b0.w, b1.x, b1.y, b1.z, b1.w};
#pragma unroll
                for (int i = 0; i < 8; ++i)
#pragma unroll
                    for (int j = 0; j < 8; ++j)
                        acc[i][j] = fmaf(a[i], b[j], acc[i][j]);
            }
            __syncthreads();
        }

        // epilogue
#pragma unroll
        for (int i = 0; i < 8; ++i) {
            int row = m0 + ty * 8 + i;
            if (row >= N) continue;
            int col = tx * 8;
            float4 o0 = make_float4(acc[i][0], acc[i][1], acc[i][2], acc[i][3]);
            float4 o1 = make_float4(acc[i][4], acc[i][5], acc[i][6], acc[i][7]);
            if (RESID) {
                float4 b0 = *(const float4*)&bias[col];
                float4 b1 = *(const float4*)&bias[col + 4];
                float4 r0 = *(const float4*)&resid[(size_t)row * D + col];
                float4 r1 = *(const float4*)&resid[(size_t)row * D + col + 4];
                o0.x += b0.x + r0.x; o0.y += b0.y + r0.y;
                o0.z += b0.z + r0.z; o0.w += b0.w + r0.w;
                o1.x += b1.x + r1.x; o1.y += b1.y + r1.y;
                o1.z += b1.z + r1.z; o1.w += b1.w + r1.w;
            }
            *(float4*)&Op[(size_t)row * D + col]     = o0;
            *(float4*)&Op[(size_t)row * D + col + 4] = o1;
        }
        __syncthreads();
    }
}

// ---------------------------------------------------------------------------
// Edge kernel: one warp per edge.
// logit = dot(Q[dst], K[src]) / sqrt(D); agg[dst] += sigmoid(logit) * V[src]
// ---------------------------------------------------------------------------
__global__ void edge_kernel(const int* __restrict__ ei,
                            const float* __restrict__ Q,
                            const float* __restrict__ K,
                            const float* __restrict__ V,
                            float* __restrict__ agg,
                            int E)
{
    int warp = (blockIdx.x * blockDim.x + threadIdx.x) >> 5;
    int lane = threadIdx.x & 31;
    if (warp >= E) return;

    int src = ei[warp];       // edge_index[0][e]
    int dst = ei[E + warp];   // edge_index[1][e]

    const float4 q = *(const float4*)&Q[(size_t)dst * D + lane * 4];
    const float4 k = *(const float4*)&K[(size_t)src * D + lane * 4];
    float d = q.x * k.x + q.y * k.y + q.z * k.z + q.w * k.w;
#pragma unroll
    for (int o = 16; o; o >>= 1) d += __shfl_xor_sync(0xffffffffu, d, o);

    // sigmoid(d / sqrt(128))
    float s = 1.0f / (1.0f + __expf(-d * 0.08838834764831845f));

    const float4 v = *(const float4*)&V[(size_t)src * D + lane * 4];
    float mx = s * v.x, my = s * v.y, mz = s * v.z, mw = s * v.w;

    float* p = &agg[(size_t)dst * D + lane * 4];
    asm volatile("red.global.add.v4.f32 [%0], {%1, %2, %3, %4};"
                 :: "l"(p), "f"(mx), "f"(my), "f"(mz), "f"(mw)
                 : "memory");
}

// ---------------------------------------------------------------------------
// LayerNorm: one block (128 threads) per row.
// ---------------------------------------------------------------------------
__global__ void ln_kernel(const float* __restrict__ H,
                          const float* __restrict__ gamma,
                          const float* __restrict__ beta,
                          float* __restrict__ out,
                          int N)
{
    int row = blockIdx.x;
    int t = threadIdx.x;   // 0..127
    float v = H[(size_t)row * D + t];
    float s = v, s2 = v * v;
#pragma unroll
    for (int o = 16; o; o >>= 1) {
        s  += __shfl_xor_sync(0xffffffffu, s,  o);
        s2 += __shfl_xor_sync(0xffffffffu, s2, o);
    }
    __shared__ float sh[8];
    int w = t >> 5, l = t & 31;
    if (l == 0) { sh[w] = s; sh[4 + w] = s2; }
    __syncthreads();
    float ts  = sh[0] + sh[1] + sh[2] + sh[3];
    float ts2 = sh[4] + sh[5] + sh[6] + sh[7];
    float mu  = ts * (1.0f / 128.0f);
    float var = ts2 * (1.0f / 128.0f) - mu * mu;
    float r   = rsqrtf(var + 1e-5f);
    out[(size_t)row * D + t] = (v - mu) * r * gamma[t] + beta[t];
}

// ---------------------------------------------------------------------------
// launch
// ---------------------------------------------------------------------------
extern "C" void kernel_launch(void* const* d_in, const int* in_sizes, int n_in,
                              void* d_out, int out_size)
{
    const float* x     = (const float*)d_in[0];
    const int*   ei    = (const int*)  d_in[1];
    const float* Wq    = (const float*)d_in[2];
    const float* Wk    = (const float*)d_in[3];
    const float* Wv    = (const float*)d_in[4];
    const float* Wo    = (const float*)d_in[5];
    const float* bo    = (const float*)d_in[6];
    const float* gamma = (const float*)d_in[7];
    const float* beta  = (const float*)d_in[8];
    float*       out   = (float*)d_out;

    const int N = in_sizes[0] / D;
    const int E = in_sizes[1] / 2;

    float *Q, *K, *V, *agg, *H;
    cudaGetSymbolAddress((void**)&Q,   g_Q);
    cudaGetSymbolAddress((void**)&K,   g_K);
    cudaGetSymbolAddress((void**)&V,   g_V);
    cudaGetSymbolAddress((void**)&agg, g_agg);
    cudaGetSymbolAddress((void**)&H,   g_H);

    const int mb = (N + 127) / 128;

    zero_kernel<<<(N * D + 511) / 512, 512>>>(agg, N * D);

    gemm_kernel<3, false><<<mb, 256>>>(x, Wq, Wk, Wv, Q, K, V, nullptr, nullptr, N);

    edge_kernel<<<(E + 7) / 8, 256>>>(ei, Q, K, V, agg, E);

    gemm_kernel<1, true><<<mb, 256>>>(agg, Wo, nullptr, nullptr, H, nullptr, nullptr, bo, x, N);

    ln_kernel<<<N, 128>>>(H, gamma, beta, out, N);
}

// round 3
// speedup vs baseline: 1.6788x; 1.6788x over previous
#include <cuda_runtime.h>
#include <cuda_bf16.h>
#include <math.h>
#include <stdint.h>

#define D 128
#define MAXN 50176   // 50000 padded up to multiple of 128

__device__ float g_Q[MAXN * D];
__device__ float g_K[MAXN * D];
__device__ float g_V[MAXN * D];
__device__ float g_agg[MAXN * D];

// smem tile stride (floats) with padding for conflict-free fragment loads
#define LDT 132
#define TILE_FLOATS (128 * LDT)
#define SMEM_BYTES (2 * TILE_FLOATS * 4)   // As + Bs = 135168 B (dynamic)

// ---------------------------------------------------------------------------
// helpers
// ---------------------------------------------------------------------------
__device__ __forceinline__ uint32_t f2tf32(float f) {
    uint32_t u;
    asm("cvt.rna.tf32.f32 %0, %1;" : "=r"(u) : "f"(f));
    return u;
}

__device__ __forceinline__ void mma_tf32(float d[4], const uint32_t a[4], const uint32_t b[2]) {
    asm volatile(
        "mma.sync.aligned.m16n8k8.row.col.f32.tf32.tf32.f32 "
        "{%0,%1,%2,%3}, {%4,%5,%6,%7}, {%8,%9}, {%0,%1,%2,%3};"
        : "+f"(d[0]), "+f"(d[1]), "+f"(d[2]), "+f"(d[3])
        : "r"(a[0]), "r"(a[1]), "r"(a[2]), "r"(a[3]), "r"(b[0]), "r"(b[1]));
}

// ---------------------------------------------------------------------------
// Shared GEMM body: loads A rows [m0, m0+128) of Xsrc and B = W (128x128),
// converts to tf32 in smem, computes the 128x128 fp32 tile into acc.
// Warp w: rows [ (w&1)*64 , +64 ), cols [ (w>>1)*32 , +32 ).
// acc[i][j][4] is the m16n8 fragment for M-tile i (0..3), N-tile j (0..3).
// ---------------------------------------------------------------------------
__device__ __forceinline__ void gemm_tile(const float* __restrict__ Xsrc,
                                          const float* __restrict__ W,
                                          float* __restrict__ As,
                                          float* __restrict__ Bs,
                                          int m0, int N,
                                          float acc[4][4][4])
{
    const int tid  = threadIdx.x;
    const int lane = tid & 31;
    const int warp = tid >> 5;

    // ---- load & convert tiles: 4096 float4 slots per tile, 16 per thread ----
    uint32_t* Au = (uint32_t*)As;
    uint32_t* Bu = (uint32_t*)Bs;
#pragma unroll
    for (int i = 0; i < 16; ++i) {
        int idx = tid + i * 256;          // 0..4095
        int m = idx >> 5;                 // row 0..127
        int c = idx & 31;                 // float4 col 0..31
        int gm = m0 + m;
        float4 f = (gm < N) ? *(const float4*)(Xsrc + (size_t)gm * D + c * 4)
                            : make_float4(0.f, 0.f, 0.f, 0.f);
        uint4 ua = make_uint4(f2tf32(f.x), f2tf32(f.y), f2tf32(f.z), f2tf32(f.w));
        *(uint4*)(Au + m * LDT + c * 4) = ua;

        float4 g = *(const float4*)(W + (size_t)m * D + c * 4);
        uint4 ub = make_uint4(f2tf32(g.x), f2tf32(g.y), f2tf32(g.z), f2tf32(g.w));
        *(uint4*)(Bu + m * LDT + c * 4) = ub;
    }
    __syncthreads();

#pragma unroll
    for (int i = 0; i < 4; ++i)
#pragma unroll
        for (int j = 0; j < 4; ++j)
#pragma unroll
            for (int t = 0; t < 4; ++t) acc[i][j][t] = 0.0f;

    const int mb = (warp & 1) * 64;
    const int nb = (warp >> 1) * 32;
    const int lq = lane >> 2;             // 0..7
    const int lr = lane & 3;              // 0..3

#pragma unroll
    for (int k0 = 0; k0 < 16; ++k0) {
        const int k = k0 * 8 + lr;
        uint32_t a[4][4], b[4][2];
#pragma unroll
        for (int i = 0; i < 4; ++i) {
            int r0 = mb + i * 16 + lq;
            a[i][0] = Au[r0 * LDT + k];
            a[i][1] = Au[(r0 + 8) * LDT + k];
            a[i][2] = Au[r0 * LDT + k + 4];
            a[i][3] = Au[(r0 + 8) * LDT + k + 4];
        }
#pragma unroll
        for (int j = 0; j < 4; ++j) {
            int c0 = nb + j * 8 + lq;
            b[j][0] = Bu[c0 * LDT + k];
            b[j][1] = Bu[c0 * LDT + k + 4];
        }
#pragma unroll
        for (int i = 0; i < 4; ++i)
#pragma unroll
            for (int j = 0; j < 4; ++j)
                mma_tf32(acc[i][j], a[i], b[j]);
    }
}

// ---------------------------------------------------------------------------
// QKV kernel: grid (mb, 3); blockIdx.y selects (Wq->Q, Wk->K, Wv->V)
// ---------------------------------------------------------------------------
__global__ void __launch_bounds__(256, 1)
qkv_kernel(const float* __restrict__ X,
           const float* __restrict__ Wq, const float* __restrict__ Wk,
           const float* __restrict__ Wv,
           float* __restrict__ Q, float* __restrict__ K, float* __restrict__ V,
           int N)
{
    extern __shared__ float smem[];
    float* As = smem;
    float* Bs = smem + TILE_FLOATS;

    const float* W = (blockIdx.y == 0) ? Wq : ((blockIdx.y == 1) ? Wk : Wv);
    float*       O = (blockIdx.y == 0) ? Q  : ((blockIdx.y == 1) ? K  : V);
    const int m0 = blockIdx.x * 128;

    float acc[4][4][4];
    gemm_tile(X, W, As, Bs, m0, N, acc);

    const int lane = threadIdx.x & 31;
    const int warp = threadIdx.x >> 5;
    const int mb = (warp & 1) * 64;
    const int nb = (warp >> 1) * 32;
    const int lq = lane >> 2;
    const int lr = lane & 3;

#pragma unroll
    for (int i = 0; i < 4; ++i) {
        int row = m0 + mb + i * 16 + lq;
#pragma unroll
        for (int j = 0; j < 4; ++j) {
            int col = nb + j * 8 + lr * 2;
            if (row < N)
                *(float2*)(O + (size_t)row * D + col) = make_float2(acc[i][j][0], acc[i][j][1]);
            if (row + 8 < N)
                *(float2*)(O + (size_t)(row + 8) * D + col) = make_float2(acc[i][j][2], acc[i][j][3]);
        }
    }
}

// ---------------------------------------------------------------------------
// O-proj + bias + residual + LayerNorm fused:
// out = LN(x + agg @ Wo^T + bo)
// ---------------------------------------------------------------------------
__global__ void __launch_bounds__(256, 1)
oproj_ln_kernel(const float* __restrict__ AGG, const float* __restrict__ Wo,
                const float* __restrict__ X,
                const float* __restrict__ bo, const float* __restrict__ gamma,
                const float* __restrict__ beta,
                float* __restrict__ out, int N)
{
    extern __shared__ float smem[];
    float* As = smem;                 // reused as H-tile after compute
    float* Bs = smem + TILE_FLOATS;
    __shared__ float P[384];          // bo | gamma | beta

    const int tid = threadIdx.x;
    if (tid < 128)      P[tid]       = bo[tid];
    else                P[tid]       = gamma[tid - 128];
    if (tid < 128)      P[256 + tid] = beta[tid];

    const int m0 = blockIdx.x * 128;

    float acc[4][4][4];
    gemm_tile(AGG, Wo, As, Bs, m0, N, acc);
    __syncthreads();   // done reading As as A-tile

    const int lane = tid & 31;
    const int warp = tid >> 5;
    const int mb = (warp & 1) * 64;
    const int nb = (warp >> 1) * 32;
    const int lq = lane >> 2;
    const int lr = lane & 3;

    // stage GEMM result tile into As (H staging, stride LDT)
#pragma unroll
    for (int i = 0; i < 4; ++i) {
        int r = mb + i * 16 + lq;
#pragma unroll
        for (int j = 0; j < 4; ++j) {
            int c = nb + j * 8 + lr * 2;
            *(float2*)(As + r * LDT + c)       = make_float2(acc[i][j][0], acc[i][j][1]);
            *(float2*)(As + (r + 8) * LDT + c) = make_float2(acc[i][j][2], acc[i][j][3]);
        }
    }
    __syncthreads();

    // LN: each warp owns rows [warp*16, warp*16+16); lane l covers cols 4l..4l+3
#pragma unroll
    for (int p = 0; p < 16; ++p) {
        int r = warp * 16 + p;
        int grow = m0 + r;
        if (grow >= N) continue;

        float4 h = *(float4*)(As + r * LDT + lane * 4);
        float4 xb = *(const float4*)(X + (size_t)grow * D + lane * 4);
        float4 bb = *(const float4*)(P + lane * 4);
        h.x += xb.x + bb.x; h.y += xb.y + bb.y;
        h.z += xb.z + bb.z; h.w += xb.w + bb.w;

        float s  = h.x + h.y + h.z + h.w;
        float s2 = h.x * h.x + h.y * h.y + h.z * h.z + h.w * h.w;
#pragma unroll
        for (int o = 16; o; o >>= 1) {
            s  += __shfl_xor_sync(0xffffffffu, s,  o);
            s2 += __shfl_xor_sync(0xffffffffu, s2, o);
        }
        float mu  = s * (1.0f / 128.0f);
        float var = s2 * (1.0f / 128.0f) - mu * mu;
        float rv  = rsqrtf(var + 1e-5f);

        float4 gm = *(const float4*)(P + 128 + lane * 4);
        float4 bt = *(const float4*)(P + 256 + lane * 4);
        float4 o;
        o.x = (h.x - mu) * rv * gm.x + bt.x;
        o.y = (h.y - mu) * rv * gm.y + bt.y;
        o.z = (h.z - mu) * rv * gm.z + bt.z;
        o.w = (h.w - mu) * rv * gm.w + bt.w;
        *(float4*)(out + (size_t)grow * D + lane * 4) = o;
    }
}

// ---------------------------------------------------------------------------
// zero kernel (float4)
// ---------------------------------------------------------------------------
__global__ void zero_kernel(float4* __restrict__ p, int n4) {
    int i = blockIdx.x * blockDim.x + threadIdx.x;
    if (i < n4) p[i] = make_float4(0.f, 0.f, 0.f, 0.f);
}

// ---------------------------------------------------------------------------
// Edge kernel: one warp per edge.
// logit = dot(Q[dst], K[src]) / sqrt(D); agg[dst] += sigmoid(logit) * V[src]
// ---------------------------------------------------------------------------
__global__ void edge_kernel(const int* __restrict__ ei,
                            const float* __restrict__ Q,
                            const float* __restrict__ K,
                            const float* __restrict__ V,
                            float* __restrict__ agg,
                            int E)
{
    int warp = (blockIdx.x * blockDim.x + threadIdx.x) >> 5;
    int lane = threadIdx.x & 31;
    if (warp >= E) return;

    int src = ei[warp];       // edge_index[0][e]
    int dst = ei[E + warp];   // edge_index[1][e]

    const float4 q = *(const float4*)&Q[(size_t)dst * D + lane * 4];
    const float4 k = *(const float4*)&K[(size_t)src * D + lane * 4];
    float d = q.x * k.x + q.y * k.y + q.z * k.z + q.w * k.w;
#pragma unroll
    for (int o = 16; o; o >>= 1) d += __shfl_xor_sync(0xffffffffu, d, o);

    float s = 1.0f / (1.0f + __expf(-d * 0.08838834764831845f));

    const float4 v = *(const float4*)&V[(size_t)src * D + lane * 4];
    float mx = s * v.x, my = s * v.y, mz = s * v.z, mw = s * v.w;

    float* p = &agg[(size_t)dst * D + lane * 4];
    asm volatile("red.global.add.v4.f32 [%0], {%1, %2, %3, %4};"
                 :: "l"(p), "f"(mx), "f"(my), "f"(mz), "f"(mw)
                 : "memory");
}

// ---------------------------------------------------------------------------
// launch
// ---------------------------------------------------------------------------
extern "C" void kernel_launch(void* const* d_in, const int* in_sizes, int n_in,
                              void* d_out, int out_size)
{
    const float* x     = (const float*)d_in[0];
    const int*   ei    = (const int*)  d_in[1];
    const float* Wq    = (const float*)d_in[2];
    const float* Wk    = (const float*)d_in[3];
    const float* Wv    = (const float*)d_in[4];
    const float* Wo    = (const float*)d_in[5];
    const float* bo    = (const float*)d_in[6];
    const float* gamma = (const float*)d_in[7];
    const float* beta  = (const float*)d_in[8];
    float*       out   = (float*)d_out;

    const int N = in_sizes[0] / D;
    const int E = in_sizes[1] / 2;

    float *Q, *K, *V, *agg;
    cudaGetSymbolAddress((void**)&Q,   g_Q);
    cudaGetSymbolAddress((void**)&K,   g_K);
    cudaGetSymbolAddress((void**)&V,   g_V);
    cudaGetSymbolAddress((void**)&agg, g_agg);

    cudaFuncSetAttribute(qkv_kernel, cudaFuncAttributeMaxDynamicSharedMemorySize, SMEM_BYTES);
    cudaFuncSetAttribute(oproj_ln_kernel, cudaFuncAttributeMaxDynamicSharedMemorySize, SMEM_BYTES);

    const int mb = (N + 127) / 128;

    zero_kernel<<<(N * D / 4 + 255) / 256, 256>>>((float4*)agg, N * D / 4);

    qkv_kernel<<<dim3(mb, 3), 256, SMEM_BYTES>>>(x, Wq, Wk, Wv, Q, K, V, N);

    edge_kernel<<<(E + 7) / 8, 256>>>(ei, Q, K, V, agg, E);

    oproj_ln_kernel<<<mb, 256, SMEM_BYTES>>>(agg, Wo, x, bo, gamma, beta, out, N);
}

// round 4
// speedup vs baseline: 1.7469x; 1.0406x over previous
#include <cuda_runtime.h>
#include <cuda_bf16.h>
#include <math.h>
#include <stdint.h>

#define D 128
#define MAXN 50176   // 50000 padded up to multiple of 128

__device__ float g_Q[MAXN * D];
__device__ float g_K[MAXN * D];
__device__ float g_V[MAXN * D];
__device__ float g_agg[MAXN * D];

// smem tile stride (floats) with padding for conflict-free fragment loads
#define LDT 132
#define TILE_FLOATS (128 * LDT)
#define QKV_SMEM (3 * TILE_FLOATS * 4)   // A + 2x B buffers = 202752 B
#define OPJ_SMEM (2 * TILE_FLOATS * 4)   // A + B = 135168 B

// ---------------------------------------------------------------------------
// helpers
// ---------------------------------------------------------------------------
__device__ __forceinline__ uint32_t f2tf32(float f) {
    uint32_t u;
    asm("cvt.rna.tf32.f32 %0, %1;" : "=r"(u) : "f"(f));
    return u;
}

__device__ __forceinline__ void mma_tf32(float d[4], const uint32_t a[4], const uint32_t b[2]) {
    asm volatile(
        "mma.sync.aligned.m16n8k8.row.col.f32.tf32.tf32.f32 "
        "{%0,%1,%2,%3}, {%4,%5,%6,%7}, {%8,%9}, {%0,%1,%2,%3};"
        : "+f"(d[0]), "+f"(d[1]), "+f"(d[2]), "+f"(d[3])
        : "r"(a[0]), "r"(a[1]), "r"(a[2]), "r"(a[3]), "r"(b[0]), "r"(b[1]));
}

// load one 128x128 fp32 tile -> tf32 smem tile (512 threads, 8 float4 each)
__device__ __forceinline__ void load_tile(const float* __restrict__ src,
                                          uint32_t* __restrict__ Tu,
                                          int m0, int N) {
    const int tid = threadIdx.x;
#pragma unroll
    for (int i = 0; i < 8; ++i) {
        int idx = tid + i * 512;          // 0..4095
        int m = idx >> 5;                 // row 0..127
        int c = idx & 31;                 // float4 col 0..31
        int gm = m0 + m;
        float4 f = (gm < N) ? *(const float4*)(src + (size_t)gm * D + c * 4)
                            : make_float4(0.f, 0.f, 0.f, 0.f);
        uint4 u = make_uint4(f2tf32(f.x), f2tf32(f.y), f2tf32(f.z), f2tf32(f.w));
        *(uint4*)(Tu + m * LDT + c * 4) = u;
    }
}

// MMA phase: warp computes its 32x32 tile from As x Bs.
// warp w: rows (w&3)*32, cols (w>>2)*32. acc[2][4][4].
__device__ __forceinline__ void mma_phase(const uint32_t* __restrict__ Au,
                                          const uint32_t* __restrict__ Bu,
                                          float acc[2][4][4]) {
    const int lane = threadIdx.x & 31;
    const int warp = threadIdx.x >> 5;
    const int mb = (warp & 3) * 32;
    const int nb = (warp >> 2) * 32;
    const int lq = lane >> 2;             // 0..7
    const int lr = lane & 3;              // 0..3

#pragma unroll
    for (int i = 0; i < 2; ++i)
#pragma unroll
        for (int j = 0; j < 4; ++j)
#pragma unroll
            for (int t = 0; t < 4; ++t) acc[i][j][t] = 0.0f;

#pragma unroll
    for (int k0 = 0; k0 < 16; ++k0) {
        const int k = k0 * 8 + lr;
        uint32_t a[2][4], b[4][2];
#pragma unroll
        for (int i = 0; i < 2; ++i) {
            int r0 = mb + i * 16 + lq;
            a[i][0] = Au[r0 * LDT + k];
            a[i][1] = Au[(r0 + 8) * LDT + k];
            a[i][2] = Au[r0 * LDT + k + 4];
            a[i][3] = Au[(r0 + 8) * LDT + k + 4];
        }
#pragma unroll
        for (int j = 0; j < 4; ++j) {
            int c0 = nb + j * 8 + lq;
            b[j][0] = Bu[c0 * LDT + k];
            b[j][1] = Bu[c0 * LDT + k + 4];
        }
#pragma unroll
        for (int i = 0; i < 2; ++i)
#pragma unroll
            for (int j = 0; j < 4; ++j)
                mma_tf32(acc[i][j], a[i], b[j]);
    }
}

// ---------------------------------------------------------------------------
// Fused QKV kernel: one CTA computes 128 rows of Q, K, V.
// A tile loaded once; B tiles double-buffered across the 3 weights.
// ---------------------------------------------------------------------------
__global__ void __launch_bounds__(512, 1)
qkv_kernel(const float* __restrict__ X,
           const float* __restrict__ Wq, const float* __restrict__ Wk,
           const float* __restrict__ Wv,
           float* __restrict__ Q, float* __restrict__ K, float* __restrict__ V,
           int N)
{
    extern __shared__ float smem[];
    uint32_t* Au = (uint32_t*)smem;
    uint32_t* Bu[2] = {(uint32_t*)(smem + TILE_FLOATS),
                       (uint32_t*)(smem + 2 * TILE_FLOATS)};

    const float* Wlist[3] = {Wq, Wk, Wv};
    float*       Olist[3] = {Q, K, V};
    const int m0 = blockIdx.x * 128;

    load_tile(X, Au, m0, N);
    load_tile(Wlist[0], Bu[0], 0, 128);
    __syncthreads();

    const int lane = threadIdx.x & 31;
    const int warp = threadIdx.x >> 5;
    const int mb = (warp & 3) * 32;
    const int nb = (warp >> 2) * 32;
    const int lq = lane >> 2;
    const int lr = lane & 3;

#pragma unroll
    for (int w = 0; w < 3; ++w) {
        // prefetch next weight into the alternate buffer
        if (w < 2) load_tile(Wlist[w + 1], Bu[(w + 1) & 1], 0, 128);

        float acc[2][4][4];
        mma_phase(Au, Bu[w & 1], acc);

        float* O = Olist[w];
#pragma unroll
        for (int i = 0; i < 2; ++i) {
            int row = m0 + mb + i * 16 + lq;
#pragma unroll
            for (int j = 0; j < 4; ++j) {
                int col = nb + j * 8 + lr * 2;
                if (row < N)
                    *(float2*)(O + (size_t)row * D + col) = make_float2(acc[i][j][0], acc[i][j][1]);
                if (row + 8 < N)
                    *(float2*)(O + (size_t)(row + 8) * D + col) = make_float2(acc[i][j][2], acc[i][j][3]);
            }
        }
        __syncthreads();   // next-B prefetch complete + all warps done with cur B
    }
}

// ---------------------------------------------------------------------------
// O-proj + bias + residual + LayerNorm fused:
// out = LN(x + agg @ Wo^T + bo)
// ---------------------------------------------------------------------------
__global__ void __launch_bounds__(512, 1)
oproj_ln_kernel(const float* __restrict__ AGG, const float* __restrict__ Wo,
                const float* __restrict__ X,
                const float* __restrict__ bo, const float* __restrict__ gamma,
                const float* __restrict__ beta,
                float* __restrict__ out, int N)
{
    extern __shared__ float smem[];
    uint32_t* Au = (uint32_t*)smem;              // A tile, then reused as H tile
    uint32_t* Bu = (uint32_t*)(smem + TILE_FLOATS);
    float* Hs = smem;                            // alias of Au
    __shared__ float P[384];                     // bo | gamma | beta

    const int tid = threadIdx.x;
    if (tid < 128)       P[tid]       = bo[tid];
    else if (tid < 256)  P[tid]       = gamma[tid - 128];
    else if (tid < 384)  P[tid]       = beta[tid - 256];

    const int m0 = blockIdx.x * 128;

    load_tile(AGG, Au, m0, N);
    load_tile(Wo, Bu, 0, 128);
    __syncthreads();

    float acc[2][4][4];
    mma_phase(Au, Bu, acc);
    __syncthreads();   // everyone done reading As/Bs

    const int lane = tid & 31;
    const int warp = tid >> 5;
    const int mb = (warp & 3) * 32;
    const int nb = (warp >> 2) * 32;
    const int lq = lane >> 2;
    const int lr = lane & 3;

    // stage GEMM result tile into Hs
#pragma unroll
    for (int i = 0; i < 2; ++i) {
        int r = mb + i * 16 + lq;
#pragma unroll
        for (int j = 0; j < 4; ++j) {
            int c = nb + j * 8 + lr * 2;
            *(float2*)(Hs + r * LDT + c)       = make_float2(acc[i][j][0], acc[i][j][1]);
            *(float2*)(Hs + (r + 8) * LDT + c) = make_float2(acc[i][j][2], acc[i][j][3]);
        }
    }
    __syncthreads();

    // LN: warp owns rows [warp*8, warp*8+8); lane l covers cols 4l..4l+3
#pragma unroll
    for (int p = 0; p < 8; ++p) {
        int r = warp * 8 + p;
        int grow = m0 + r;
        if (grow >= N) continue;

        float4 h = *(float4*)(Hs + r * LDT + lane * 4);
        float4 xb = *(const float4*)(X + (size_t)grow * D + lane * 4);
        float4 bb = *(const float4*)(P + lane * 4);
        h.x += xb.x + bb.x; h.y += xb.y + bb.y;
        h.z += xb.z + bb.z; h.w += xb.w + bb.w;

        float s  = h.x + h.y + h.z + h.w;
        float s2 = h.x * h.x + h.y * h.y + h.z * h.z + h.w * h.w;
#pragma unroll
        for (int o = 16; o; o >>= 1) {
            s  += __shfl_xor_sync(0xffffffffu, s,  o);
            s2 += __shfl_xor_sync(0xffffffffu, s2, o);
        }
        float mu  = s * (1.0f / 128.0f);
        float var = s2 * (1.0f / 128.0f) - mu * mu;
        float rv  = rsqrtf(var + 1e-5f);

        float4 gm = *(const float4*)(P + 128 + lane * 4);
        float4 bt = *(const float4*)(P + 256 + lane * 4);
        float4 o;
        o.x = (h.x - mu) * rv * gm.x + bt.x;
        o.y = (h.y - mu) * rv * gm.y + bt.y;
        o.z = (h.z - mu) * rv * gm.z + bt.z;
        o.w = (h.w - mu) * rv * gm.w + bt.w;
        *(float4*)(out + (size_t)grow * D + lane * 4) = o;
    }
}

// ---------------------------------------------------------------------------
// zero kernel (float4)
// ---------------------------------------------------------------------------
__global__ void zero_kernel(float4* __restrict__ p, int n4) {
    int i = blockIdx.x * blockDim.x + threadIdx.x;
    if (i < n4) p[i] = make_float4(0.f, 0.f, 0.f, 0.f);
}

// ---------------------------------------------------------------------------
// Edge kernel: one warp per edge.
// logit = dot(Q[dst], K[src]) / sqrt(D); agg[dst] += sigmoid(logit) * V[src]
// ---------------------------------------------------------------------------
__global__ void edge_kernel(const int* __restrict__ ei,
                            const float* __restrict__ Q,
                            const float* __restrict__ K,
                            const float* __restrict__ V,
                            float* __restrict__ agg,
                            int E)
{
    int warp = (blockIdx.x * blockDim.x + threadIdx.x) >> 5;
    int lane = threadIdx.x & 31;
    if (warp >= E) return;

    int src = ei[warp];       // edge_index[0][e]
    int dst = ei[E + warp];   // edge_index[1][e]

    const float4 q = *(const float4*)&Q[(size_t)dst * D + lane * 4];
    const float4 k = *(const float4*)&K[(size_t)src * D + lane * 4];
    float d = q.x * k.x + q.y * k.y + q.z * k.z + q.w * k.w;
#pragma unroll
    for (int o = 16; o; o >>= 1) d += __shfl_xor_sync(0xffffffffu, d, o);

    float s = 1.0f / (1.0f + __expf(-d * 0.08838834764831845f));

    const float4 v = *(const float4*)&V[(size_t)src * D + lane * 4];
    float mx = s * v.x, my = s * v.y, mz = s * v.z, mw = s * v.w;

    float* p = &agg[(size_t)dst * D + lane * 4];
    asm volatile("red.global.add.v4.f32 [%0], {%1, %2, %3, %4};"
                 :: "l"(p), "f"(mx), "f"(my), "f"(mz), "f"(mw)
                 : "memory");
}

// ---------------------------------------------------------------------------
// launch
// ---------------------------------------------------------------------------
extern "C" void kernel_launch(void* const* d_in, const int* in_sizes, int n_in,
                              void* d_out, int out_size)
{
    const float* x     = (const float*)d_in[0];
    const int*   ei    = (const int*)  d_in[1];
    const float* Wq    = (const float*)d_in[2];
    const float* Wk    = (const float*)d_in[3];
    const float* Wv    = (const float*)d_in[4];
    const float* Wo    = (const float*)d_in[5];
    const float* bo    = (const float*)d_in[6];
    const float* gamma = (const float*)d_in[7];
    const float* beta  = (const float*)d_in[8];
    float*       out   = (float*)d_out;

    const int N = in_sizes[0] / D;
    const int E = in_sizes[1] / 2;

    float *Q, *K, *V, *agg;
    cudaGetSymbolAddress((void**)&Q,   g_Q);
    cudaGetSymbolAddress((void**)&K,   g_K);
    cudaGetSymbolAddress((void**)&V,   g_V);
    cudaGetSymbolAddress((void**)&agg, g_agg);

    cudaFuncSetAttribute(qkv_kernel, cudaFuncAttributeMaxDynamicSharedMemorySize, QKV_SMEM);
    cudaFuncSetAttribute(oproj_ln_kernel, cudaFuncAttributeMaxDynamicSharedMemorySize, OPJ_SMEM);

    const int mb = (N + 127) / 128;

    zero_kernel<<<(N * D / 4 + 255) / 256, 256>>>((float4*)agg, N * D / 4);

    qkv_kernel<<<mb, 512, QKV_SMEM>>>(x, Wq, Wk, Wv, Q, K, V, N);

    edge_kernel<<<(E + 7) / 8, 256>>>(ei, Q, K, V, agg, E);

    oproj_ln_kernel<<<mb, 512, OPJ_SMEM>>>(agg, Wo, x, bo, gamma, beta, out, N);
}